// round 1
// baseline (speedup 1.0000x reference)
#include <cuda_runtime.h>
#include <cuda_bf16.h>
#include <math.h>

// Problem constants
#define B_   128
#define N_   197
#define C_   768
#define H_   12
#define HD_  64
#define NC3_ 2304          // 3*C
#define M_   (B_ * N_)     // 25216
#define NREL (38809)       // 197*197
#define SCALE 0.125f       // 64^-0.5

// ---------------------------------------------------------------------------
// Scratch (static __device__ globals — allocation-free per harness rules)
// ---------------------------------------------------------------------------
__device__ float g_Q[B_ * H_ * N_ * HD_];   // pre-scaled, biased
__device__ float g_K[B_ * H_ * N_ * HD_];
__device__ float g_V[B_ * H_ * N_ * HD_];   // biased
__device__ float g_O[M_ * C_];              // attention output [B,N,C]
__device__ float g_RB[H_ * NREL];           // rel bias [H,N,N]

// ---------------------------------------------------------------------------
// Relative position bias gather: g_RB[h][n][m] = table[idx[n][m]][h]
// ---------------------------------------------------------------------------
__global__ void relbias_kernel(const float* __restrict__ table,
                               const int* __restrict__ idx) {
    int i = blockIdx.x * 256 + threadIdx.x;
    if (i < H_ * NREL) {
        int h = i / NREL;
        int r = i - h * NREL;
        g_RB[i] = table[idx[r] * H_ + h];
    }
}

// ---------------------------------------------------------------------------
// SIMT fp32 GEMM core: C[128x128] tile of A(MxK, row-major) * W(NxK, row-major)^T
// BK=8, 256 threads, 8x8 per thread, double-buffered smem.
// ---------------------------------------------------------------------------
#define BM 128
#define BN 128
#define BK 8

__device__ __forceinline__ void sgemm_tile_core(
    const float* __restrict__ A, const float* __restrict__ W,
    int K, float c[8][8])
{
    __shared__ float As[2][BK][BM];
    __shared__ float Bs[2][BK][BM];

    const int tid = threadIdx.x;
    const int tx = tid & 15;
    const int ty = tid >> 4;
    const int brow = blockIdx.y * BM;
    const int bcol = blockIdx.x * BN;

    const int ar = tid >> 1;            // tile row served by this thread
    const int ac = (tid & 1) << 2;      // k offset (0 or 4)
    const float* Aptr = A + (size_t)(brow + ar) * K + ac;
    const float* Wptr = W + (size_t)(bcol + ar) * K + ac;

    // preload tile 0
    float4 av = *(const float4*)Aptr;
    float4 bv = *(const float4*)Wptr;
    As[0][ac + 0][ar] = av.x; As[0][ac + 1][ar] = av.y;
    As[0][ac + 2][ar] = av.z; As[0][ac + 3][ar] = av.w;
    Bs[0][ac + 0][ar] = bv.x; Bs[0][ac + 1][ar] = bv.y;
    Bs[0][ac + 2][ar] = bv.z; Bs[0][ac + 3][ar] = bv.w;
    __syncthreads();

    const int nTiles = K / BK;
    for (int t = 0; t < nTiles; ++t) {
        const int cur = t & 1;
        const int nxt = cur ^ 1;
        const bool more = (t + 1) < nTiles;
        if (more) {
            av = *(const float4*)(Aptr + (t + 1) * BK);
            bv = *(const float4*)(Wptr + (t + 1) * BK);
        }
        #pragma unroll
        for (int kk = 0; kk < BK; ++kk) {
            float4 a0 = *(const float4*)&As[cur][kk][ty * 4];
            float4 a1 = *(const float4*)&As[cur][kk][64 + ty * 4];
            float4 b0 = *(const float4*)&Bs[cur][kk][tx * 4];
            float4 b1 = *(const float4*)&Bs[cur][kk][64 + tx * 4];
            float a[8] = {a0.x, a0.y, a0.z, a0.w, a1.x, a1.y, a1.z, a1.w};
            float b[8] = {b0.x, b0.y, b0.z, b0.w, b1.x, b1.y, b1.z, b1.w};
            #pragma unroll
            for (int i = 0; i < 8; ++i)
                #pragma unroll
                for (int j = 0; j < 8; ++j)
                    c[i][j] += a[i] * b[j];
        }
        if (more) {
            As[nxt][ac + 0][ar] = av.x; As[nxt][ac + 1][ar] = av.y;
            As[nxt][ac + 2][ar] = av.z; As[nxt][ac + 3][ar] = av.w;
            Bs[nxt][ac + 0][ar] = bv.x; Bs[nxt][ac + 1][ar] = bv.y;
            Bs[nxt][ac + 2][ar] = bv.z; Bs[nxt][ac + 3][ar] = bv.w;
        }
        __syncthreads();
    }
}

// ---------------------------------------------------------------------------
// QKV GEMM: x[M,768] @ qkv_w[2304,768]^T, epilogue scatters to g_Q/g_K/g_V
// with composite bias (q_bias, 0, v_bias); Q pre-scaled by 1/8.
// ---------------------------------------------------------------------------
__global__ __launch_bounds__(256, 2)
void qkv_kernel(const float* __restrict__ x, const float* __restrict__ qkv_w,
                const float* __restrict__ q_bias, const float* __restrict__ v_bias)
{
    float c[8][8];
    #pragma unroll
    for (int i = 0; i < 8; ++i)
        #pragma unroll
        for (int j = 0; j < 8; ++j) c[i][j] = 0.0f;

    sgemm_tile_core(x, qkv_w, C_, c);

    const int tx = threadIdx.x & 15;
    const int ty = threadIdx.x >> 4;
    const int brow = blockIdx.y * BM;
    const int bcol = blockIdx.x * BN;

    #pragma unroll
    for (int i = 0; i < 8; ++i) {
        int row = brow + ((i < 4) ? (ty * 4 + i) : (64 + ty * 4 + (i - 4)));
        int b = row / N_;
        int n = row - b * N_;
        #pragma unroll
        for (int j = 0; j < 8; ++j) {
            int col = bcol + ((j < 4) ? (tx * 4 + j) : (64 + tx * 4 + (j - 4)));
            int which = col / C_;
            int cc = col - which * C_;
            int h = cc >> 6;
            int d = cc & 63;
            int dst = (((b * H_ + h) * N_) + n) * HD_ + d;
            float v = c[i][j];
            if (which == 0)      g_Q[dst] = (v + q_bias[cc]) * SCALE;
            else if (which == 1) g_K[dst] = v;
            else                 g_V[dst] = v + v_bias[cc];
        }
    }
}

// ---------------------------------------------------------------------------
// Proj GEMM: g_O[M,768] @ proj_w[768,768]^T + proj_b -> d_out
// ---------------------------------------------------------------------------
__global__ __launch_bounds__(256, 2)
void proj_kernel(const float* __restrict__ proj_w,
                 const float* __restrict__ proj_b, float* __restrict__ out)
{
    float c[8][8];
    #pragma unroll
    for (int i = 0; i < 8; ++i)
        #pragma unroll
        for (int j = 0; j < 8; ++j) c[i][j] = 0.0f;

    sgemm_tile_core(g_O, proj_w, C_, c);

    const int tx = threadIdx.x & 15;
    const int ty = threadIdx.x >> 4;
    const int brow = blockIdx.y * BM;
    const int bcol = blockIdx.x * BN;

    #pragma unroll
    for (int i = 0; i < 8; ++i) {
        int row = brow + ((i < 4) ? (ty * 4 + i) : (64 + ty * 4 + (i - 4)));
        #pragma unroll
        for (int j = 0; j < 8; ++j) {
            int col = bcol + ((j < 4) ? (tx * 4 + j) : (64 + tx * 4 + (j - 4)));
            out[(size_t)row * C_ + col] = c[i][j] + proj_b[col];
        }
    }
}

// ---------------------------------------------------------------------------
// Fused attention: one CTA per (b,h). K/V resident in smem (padded stride 65),
// per-warp row softmax, probs staged through smem for the PV phase.
// ---------------------------------------------------------------------------
#define KV_STRIDE 65
#define PROB_STRIDE 200
#define ATTN_SMEM_FLOATS (2 * N_ * KV_STRIDE + 8 * PROB_STRIDE)

__global__ __launch_bounds__(256)
void attn_kernel()
{
    extern __shared__ float sm[];
    float* Ks = sm;
    float* Vs = sm + N_ * KV_STRIDE;
    float* probs = sm + 2 * N_ * KV_STRIDE;

    const int bh = blockIdx.x;       // 0 .. B*H-1
    const int h = bh % H_;
    const int b = bh / H_;
    const int tid = threadIdx.x;
    const int lane = tid & 31;
    const int w = tid >> 5;

    const float* Kg = g_K + (size_t)bh * N_ * HD_;
    const float* Vg = g_V + (size_t)bh * N_ * HD_;
    for (int i = tid; i < N_ * HD_; i += 256) {
        int m = i >> 6, d = i & 63;
        Ks[m * KV_STRIDE + d] = Kg[i];
        Vs[m * KV_STRIDE + d] = Vg[i];
    }
    __syncthreads();

    const float* rb = g_RB + (size_t)h * NREL;
    float* pw = probs + w * PROB_STRIDE;

    for (int n = w; n < N_; n += 8) {
        const float* q = g_Q + ((size_t)bh * N_ + n) * HD_;
        float qv[HD_];
        #pragma unroll
        for (int d = 0; d < HD_; ++d) qv[d] = __ldg(&q[d]);

        float s[7];
        #pragma unroll
        for (int j = 0; j < 7; ++j) {
            int m = lane + j * 32;
            if (m < N_) {
                const float* kr = Ks + m * KV_STRIDE;
                float s0 = 0.f, s1 = 0.f, s2 = 0.f, s3 = 0.f;
                #pragma unroll
                for (int d = 0; d < HD_; d += 4) {
                    s0 += qv[d]     * kr[d];
                    s1 += qv[d + 1] * kr[d + 1];
                    s2 += qv[d + 2] * kr[d + 2];
                    s3 += qv[d + 3] * kr[d + 3];
                }
                s[j] = (s0 + s1) + (s2 + s3) + rb[n * N_ + m];
            } else {
                s[j] = -3.4e38f;
            }
        }
        float mx = s[0];
        #pragma unroll
        for (int j = 1; j < 7; ++j) mx = fmaxf(mx, s[j]);
        #pragma unroll
        for (int o = 16; o > 0; o >>= 1)
            mx = fmaxf(mx, __shfl_xor_sync(0xffffffffu, mx, o));

        float sum = 0.f;
        #pragma unroll
        for (int j = 0; j < 7; ++j) {
            s[j] = __expf(s[j] - mx);   // invalid lanes: exp(-huge) -> 0
            sum += s[j];
        }
        #pragma unroll
        for (int o = 16; o > 0; o >>= 1)
            sum += __shfl_xor_sync(0xffffffffu, sum, o);
        float inv = 1.0f / sum;

        #pragma unroll
        for (int j = 0; j < 7; ++j) {
            int m = lane + j * 32;
            if (m < N_) pw[m] = s[j] * inv;
        }
        __syncwarp();

        float acc0 = 0.f, acc1 = 0.f, acc2 = 0.f, acc3 = 0.f;
        #pragma unroll 4
        for (int m = 0; m < N_ - 1; m += 2) {
            float p0 = pw[m];
            float p1 = pw[m + 1];
            acc0 += p0 * Vs[m * KV_STRIDE + lane];
            acc1 += p0 * Vs[m * KV_STRIDE + 32 + lane];
            acc2 += p1 * Vs[(m + 1) * KV_STRIDE + lane];
            acc3 += p1 * Vs[(m + 1) * KV_STRIDE + 32 + lane];
        }
        {
            float p = pw[N_ - 1];
            acc0 += p * Vs[(N_ - 1) * KV_STRIDE + lane];
            acc1 += p * Vs[(N_ - 1) * KV_STRIDE + 32 + lane];
        }
        float* o = g_O + ((size_t)(b * N_ + n)) * C_ + h * HD_;
        o[lane]      = acc0 + acc2;
        o[lane + 32] = acc1 + acc3;
        __syncwarp();
    }
}

// ---------------------------------------------------------------------------
// Launch
// ---------------------------------------------------------------------------
extern "C" void kernel_launch(void* const* d_in, const int* in_sizes, int n_in,
                              void* d_out, int out_size)
{
    (void)in_sizes; (void)n_in; (void)out_size;
    const float* x      = (const float*)d_in[0];
    const float* qkv_w  = (const float*)d_in[1];
    const float* q_bias = (const float*)d_in[2];
    const float* v_bias = (const float*)d_in[3];
    const float* table  = (const float*)d_in[4];
    const float* proj_w = (const float*)d_in[5];
    const float* proj_b = (const float*)d_in[6];
    const int*   ridx   = (const int*)d_in[7];
    float* out = (float*)d_out;

    const int attn_smem = ATTN_SMEM_FLOATS * (int)sizeof(float);
    cudaFuncSetAttribute(attn_kernel,
                         cudaFuncAttributeMaxDynamicSharedMemorySize, attn_smem);

    relbias_kernel<<<(H_ * NREL + 255) / 256, 256>>>(table, ridx);
    qkv_kernel<<<dim3(NC3_ / BN, M_ / BM), 256>>>(x, qkv_w, q_bias, v_bias);
    attn_kernel<<<B_ * H_, 256, attn_smem>>>();
    proj_kernel<<<dim3(C_ / BN, M_ / BM), 256>>>(proj_w, proj_b, out);
}

// round 2
// speedup vs baseline: 1.3830x; 1.3830x over previous
#include <cuda_runtime.h>
#include <cuda_bf16.h>
#include <math.h>
#include <stdint.h>

// Problem constants
#define B_   128
#define N_   197
#define C_   768
#define H_   12
#define HD_  64
#define NC3_ 2304          // 3*C
#define M_   (B_ * N_)     // 25216
#define NREL (38809)       // 197*197
#define SCALE 0.125f       // 64^-0.5

// ---------------------------------------------------------------------------
// Scratch
// ---------------------------------------------------------------------------
__device__ float g_Q[B_ * H_ * N_ * HD_];
__device__ float g_K[B_ * H_ * N_ * HD_];
__device__ float g_V[B_ * H_ * N_ * HD_];
__device__ float g_O[M_ * C_];
__device__ float g_RB[H_ * NREL];

// ---------------------------------------------------------------------------
// relbias gather
// ---------------------------------------------------------------------------
__global__ void relbias_kernel(const float* __restrict__ table,
                               const int* __restrict__ idx) {
    int i = blockIdx.x * 256 + threadIdx.x;
    if (i < H_ * NREL) {
        int h = i / NREL;
        int r = i - h * NREL;
        g_RB[i] = table[idx[r] * H_ + h];
    }
}

// ---------------------------------------------------------------------------
// TF32 tensor-core GEMM core: 128x128 tile of A(MxK) * W(NxK)^T
// 256 threads = 8 warps (4 along M x 2 along N), warp tile 32x64.
// mma.sync.m16n8k8.tf32, smem pitch 20 (conflict-free fragment loads),
// register-staged double buffering.
// ---------------------------------------------------------------------------
#define SPITCH 20

__device__ __forceinline__ uint32_t f2tf(float x) {
    uint32_t u;
    asm("cvt.rna.tf32.f32 %0, %1;" : "=r"(u) : "f"(x));
    return u;
}

__device__ __forceinline__ void mma_tf32(float c[4], const uint32_t a[4],
                                         uint32_t b0, uint32_t b1) {
    asm volatile(
        "mma.sync.aligned.m16n8k8.row.col.f32.tf32.tf32.f32 "
        "{%0,%1,%2,%3}, {%4,%5,%6,%7}, {%8,%9}, {%0,%1,%2,%3};"
        : "+f"(c[0]), "+f"(c[1]), "+f"(c[2]), "+f"(c[3])
        : "r"(a[0]), "r"(a[1]), "r"(a[2]), "r"(a[3]), "r"(b0), "r"(b1));
}

__device__ __forceinline__ void tf32_core(const float* __restrict__ A,
                                          const float* __restrict__ W,
                                          int K, float acc[2][8][4])
{
    __shared__ uint32_t As[2][128 * SPITCH];
    __shared__ uint32_t Ws[2][128 * SPITCH];

    const int tid  = threadIdx.x;
    const int lane = tid & 31;
    const int warp = tid >> 5;
    const int wm   = warp & 3;          // 0..3 (M)
    const int wn   = warp >> 2;         // 0..1 (N)
    const int brow = blockIdx.y * 128;
    const int bcol = blockIdx.x * 128;

    const int lr = tid >> 1;            // 0..127 tile row
    const int lk = (tid & 1) * 8;       // 0 or 8
    const float* Ap = A + (size_t)(brow + lr) * K + lk;
    const float* Wp = W + (size_t)(bcol + lr) * K + lk;

    float4 a0 = *(const float4*)Ap;
    float4 a1 = *(const float4*)(Ap + 4);
    float4 w0 = *(const float4*)Wp;
    float4 w1 = *(const float4*)(Wp + 4);

    auto store_tiles = [&](int buf, float4 va0, float4 va1, float4 vw0, float4 vw1) {
        uint32_t* pa = &As[buf][lr * SPITCH + lk];
        pa[0] = f2tf(va0.x); pa[1] = f2tf(va0.y); pa[2] = f2tf(va0.z); pa[3] = f2tf(va0.w);
        pa[4] = f2tf(va1.x); pa[5] = f2tf(va1.y); pa[6] = f2tf(va1.z); pa[7] = f2tf(va1.w);
        uint32_t* pw = &Ws[buf][lr * SPITCH + lk];
        pw[0] = f2tf(vw0.x); pw[1] = f2tf(vw0.y); pw[2] = f2tf(vw0.z); pw[3] = f2tf(vw0.w);
        pw[4] = f2tf(vw1.x); pw[5] = f2tf(vw1.y); pw[6] = f2tf(vw1.z); pw[7] = f2tf(vw1.w);
    };

    store_tiles(0, a0, a1, w0, w1);
    __syncthreads();

    const int nT = K / 16;
    const int r0 = wm * 32 + (lane >> 2);
    const int cq = lane & 3;

    for (int t = 0; t < nT; ++t) {
        const int cur  = t & 1;
        const int nxt  = cur ^ 1;
        const bool more = (t + 1) < nT;
        if (more) {
            const float* Apn = Ap + (t + 1) * 16;
            const float* Wpn = Wp + (t + 1) * 16;
            a0 = *(const float4*)Apn;
            a1 = *(const float4*)(Apn + 4);
            w0 = *(const float4*)Wpn;
            w1 = *(const float4*)(Wpn + 4);
        }
        #pragma unroll
        for (int kk = 0; kk < 16; kk += 8) {
            const int c0 = kk + cq;
            uint32_t af[2][4];
            #pragma unroll
            for (int mi = 0; mi < 2; ++mi) {
                int rr = r0 + mi * 16;
                af[mi][0] = As[cur][(rr)      * SPITCH + c0];
                af[mi][1] = As[cur][(rr + 8)  * SPITCH + c0];
                af[mi][2] = As[cur][(rr)      * SPITCH + c0 + 4];
                af[mi][3] = As[cur][(rr + 8)  * SPITCH + c0 + 4];
            }
            #pragma unroll
            for (int ni = 0; ni < 8; ++ni) {
                int nb = wn * 64 + ni * 8 + (lane >> 2);
                uint32_t b0 = Ws[cur][nb * SPITCH + c0];
                uint32_t b1 = Ws[cur][nb * SPITCH + c0 + 4];
                mma_tf32(acc[0][ni], af[0], b0, b1);
                mma_tf32(acc[1][ni], af[1], b0, b1);
            }
        }
        if (more) store_tiles(nxt, a0, a1, w0, w1);
        __syncthreads();
    }
}

// ---------------------------------------------------------------------------
// QKV GEMM + scatter epilogue
// ---------------------------------------------------------------------------
__global__ __launch_bounds__(256)
void qkv_kernel(const float* __restrict__ x, const float* __restrict__ qkv_w,
                const float* __restrict__ q_bias, const float* __restrict__ v_bias)
{
    float acc[2][8][4];
    #pragma unroll
    for (int i = 0; i < 2; ++i)
        #pragma unroll
        for (int j = 0; j < 8; ++j)
            #pragma unroll
            for (int k = 0; k < 4; ++k) acc[i][j][k] = 0.f;

    tf32_core(x, qkv_w, C_, acc);

    const int lane = threadIdx.x & 31;
    const int warp = threadIdx.x >> 5;
    const int wm = warp & 3, wn = warp >> 2;
    const int brow = blockIdx.y * 128;
    const int bcol = blockIdx.x * 128;

    const int which = bcol / C_;            // block never straddles q/k/v (768%128==0)
    const int ccbase = bcol - which * C_;

    #pragma unroll
    for (int mi = 0; mi < 2; ++mi) {
        #pragma unroll
        for (int rh = 0; rh < 2; ++rh) {
            int row = brow + wm * 32 + mi * 16 + (lane >> 2) + rh * 8;
            int b = row / N_;
            int n = row - b * N_;
            #pragma unroll
            for (int ni = 0; ni < 8; ++ni) {
                #pragma unroll
                for (int cj = 0; cj < 2; ++cj) {
                    int cc = ccbase + wn * 64 + ni * 8 + (lane & 3) * 2 + cj;
                    int h = cc >> 6;
                    int d = cc & 63;
                    size_t dst = (((size_t)(b * H_ + h) * N_) + n) * HD_ + d;
                    float v = acc[mi][ni][rh * 2 + cj];
                    if (which == 0)      g_Q[dst] = (v + q_bias[cc]) * SCALE;
                    else if (which == 1) g_K[dst] = v;
                    else                 g_V[dst] = v + v_bias[cc];
                }
            }
        }
    }
}

// ---------------------------------------------------------------------------
// Proj GEMM + bias epilogue
// ---------------------------------------------------------------------------
__global__ __launch_bounds__(256)
void proj_kernel(const float* __restrict__ proj_w,
                 const float* __restrict__ proj_b, float* __restrict__ out)
{
    float acc[2][8][4];
    #pragma unroll
    for (int i = 0; i < 2; ++i)
        #pragma unroll
        for (int j = 0; j < 8; ++j)
            #pragma unroll
            for (int k = 0; k < 4; ++k) acc[i][j][k] = 0.f;

    tf32_core(g_O, proj_w, C_, acc);

    const int lane = threadIdx.x & 31;
    const int warp = threadIdx.x >> 5;
    const int wm = warp & 3, wn = warp >> 2;
    const int brow = blockIdx.y * 128;
    const int bcol = blockIdx.x * 128;

    #pragma unroll
    for (int mi = 0; mi < 2; ++mi) {
        #pragma unroll
        for (int rh = 0; rh < 2; ++rh) {
            int row = brow + wm * 32 + mi * 16 + (lane >> 2) + rh * 8;
            #pragma unroll
            for (int ni = 0; ni < 8; ++ni) {
                #pragma unroll
                for (int cj = 0; cj < 2; ++cj) {
                    int col = bcol + wn * 64 + ni * 8 + (lane & 3) * 2 + cj;
                    out[(size_t)row * C_ + col] = acc[mi][ni][rh * 2 + cj] + proj_b[col];
                }
            }
        }
    }
}

// ---------------------------------------------------------------------------
// Fused attention (unchanged from R1 — next round's target)
// ---------------------------------------------------------------------------
#define KV_STRIDE 65
#define PROB_STRIDE 200
#define ATTN_SMEM_FLOATS (2 * N_ * KV_STRIDE + 8 * PROB_STRIDE)

__global__ __launch_bounds__(256)
void attn_kernel()
{
    extern __shared__ float sm[];
    float* Ks = sm;
    float* Vs = sm + N_ * KV_STRIDE;
    float* probs = sm + 2 * N_ * KV_STRIDE;

    const int bh = blockIdx.x;
    const int h = bh % H_;
    const int b = bh / H_;
    const int tid = threadIdx.x;
    const int lane = tid & 31;
    const int w = tid >> 5;

    const float* Kg = g_K + (size_t)bh * N_ * HD_;
    const float* Vg = g_V + (size_t)bh * N_ * HD_;
    for (int i = tid; i < N_ * HD_; i += 256) {
        int m = i >> 6, d = i & 63;
        Ks[m * KV_STRIDE + d] = Kg[i];
        Vs[m * KV_STRIDE + d] = Vg[i];
    }
    __syncthreads();

    const float* rb = g_RB + (size_t)h * NREL;
    float* pw = probs + w * PROB_STRIDE;

    for (int n = w; n < N_; n += 8) {
        const float* q = g_Q + ((size_t)bh * N_ + n) * HD_;
        float qv[HD_];
        #pragma unroll
        for (int d = 0; d < HD_; ++d) qv[d] = __ldg(&q[d]);

        float s[7];
        #pragma unroll
        for (int j = 0; j < 7; ++j) {
            int m = lane + j * 32;
            if (m < N_) {
                const float* kr = Ks + m * KV_STRIDE;
                float s0 = 0.f, s1 = 0.f, s2 = 0.f, s3 = 0.f;
                #pragma unroll
                for (int d = 0; d < HD_; d += 4) {
                    s0 += qv[d]     * kr[d];
                    s1 += qv[d + 1] * kr[d + 1];
                    s2 += qv[d + 2] * kr[d + 2];
                    s3 += qv[d + 3] * kr[d + 3];
                }
                s[j] = (s0 + s1) + (s2 + s3) + rb[n * N_ + m];
            } else {
                s[j] = -3.4e38f;
            }
        }
        float mx = s[0];
        #pragma unroll
        for (int j = 1; j < 7; ++j) mx = fmaxf(mx, s[j]);
        #pragma unroll
        for (int o = 16; o > 0; o >>= 1)
            mx = fmaxf(mx, __shfl_xor_sync(0xffffffffu, mx, o));

        float sum = 0.f;
        #pragma unroll
        for (int j = 0; j < 7; ++j) {
            s[j] = __expf(s[j] - mx);
            sum += s[j];
        }
        #pragma unroll
        for (int o = 16; o > 0; o >>= 1)
            sum += __shfl_xor_sync(0xffffffffu, sum, o);
        float inv = 1.0f / sum;

        #pragma unroll
        for (int j = 0; j < 7; ++j) {
            int m = lane + j * 32;
            if (m < N_) pw[m] = s[j] * inv;
        }
        __syncwarp();

        float acc0 = 0.f, acc1 = 0.f, acc2 = 0.f, acc3 = 0.f;
        #pragma unroll 4
        for (int m = 0; m < N_ - 1; m += 2) {
            float p0 = pw[m];
            float p1 = pw[m + 1];
            acc0 += p0 * Vs[m * KV_STRIDE + lane];
            acc1 += p0 * Vs[m * KV_STRIDE + 32 + lane];
            acc2 += p1 * Vs[(m + 1) * KV_STRIDE + lane];
            acc3 += p1 * Vs[(m + 1) * KV_STRIDE + 32 + lane];
        }
        {
            float p = pw[N_ - 1];
            acc0 += p * Vs[(N_ - 1) * KV_STRIDE + lane];
            acc1 += p * Vs[(N_ - 1) * KV_STRIDE + 32 + lane];
        }
        float* o = g_O + ((size_t)(b * N_ + n)) * C_ + h * HD_;
        o[lane]      = acc0 + acc2;
        o[lane + 32] = acc1 + acc3;
        __syncwarp();
    }
}

// ---------------------------------------------------------------------------
// Launch
// ---------------------------------------------------------------------------
extern "C" void kernel_launch(void* const* d_in, const int* in_sizes, int n_in,
                              void* d_out, int out_size)
{
    (void)in_sizes; (void)n_in; (void)out_size;
    const float* x      = (const float*)d_in[0];
    const float* qkv_w  = (const float*)d_in[1];
    const float* q_bias = (const float*)d_in[2];
    const float* v_bias = (const float*)d_in[3];
    const float* table  = (const float*)d_in[4];
    const float* proj_w = (const float*)d_in[5];
    const float* proj_b = (const float*)d_in[6];
    const int*   ridx   = (const int*)d_in[7];
    float* out = (float*)d_out;

    const int attn_smem = ATTN_SMEM_FLOATS * (int)sizeof(float);
    cudaFuncSetAttribute(attn_kernel,
                         cudaFuncAttributeMaxDynamicSharedMemorySize, attn_smem);

    relbias_kernel<<<(H_ * NREL + 255) / 256, 256>>>(table, ridx);
    qkv_kernel<<<dim3(NC3_ / 128, M_ / 128), 256>>>(x, qkv_w, q_bias, v_bias);
    attn_kernel<<<B_ * H_, 256, attn_smem>>>();
    proj_kernel<<<dim3(C_ / 128, M_ / 128), 256>>>(proj_w, proj_b, out);
}

// round 3
// speedup vs baseline: 1.9270x; 1.3933x over previous
#include <cuda_runtime.h>
#include <cuda_bf16.h>
#include <math.h>
#include <stdint.h>

// Problem constants
#define B_   128
#define N_   197
#define C_   768
#define H_   12
#define HD_  64
#define NC3_ 2304
#define M_   (B_ * N_)     // 25216
#define NREL (38809)       // 197*197
#define SCALE 0.125f

// ---------------------------------------------------------------------------
// Scratch
// ---------------------------------------------------------------------------
__device__ float g_Q[B_ * H_ * N_ * HD_];
__device__ float g_K[B_ * H_ * N_ * HD_];
__device__ float g_V[B_ * H_ * N_ * HD_];
__device__ float g_O[M_ * C_];
__device__ float g_RB[H_ * NREL];

// ---------------------------------------------------------------------------
// relbias gather
// ---------------------------------------------------------------------------
__global__ void relbias_kernel(const float* __restrict__ table,
                               const int* __restrict__ idx) {
    int i = blockIdx.x * 256 + threadIdx.x;
    if (i < H_ * NREL) {
        int h = i / NREL;
        int r = i - h * NREL;
        g_RB[i] = table[idx[r] * H_ + h];
    }
}

// ---------------------------------------------------------------------------
// TF32 helpers
// ---------------------------------------------------------------------------
__device__ __forceinline__ uint32_t f2tf(float x) {
    uint32_t u;
    asm("cvt.rna.tf32.f32 %0, %1;" : "=r"(u) : "f"(x));
    return u;
}

__device__ __forceinline__ void mma_tf32(float c[4], const uint32_t a[4],
                                         uint32_t b0, uint32_t b1) {
    asm volatile(
        "mma.sync.aligned.m16n8k8.row.col.f32.tf32.tf32.f32 "
        "{%0,%1,%2,%3}, {%4,%5,%6,%7}, {%8,%9}, {%0,%1,%2,%3};"
        : "+f"(c[0]), "+f"(c[1]), "+f"(c[2]), "+f"(c[3])
        : "r"(a[0]), "r"(a[1]), "r"(a[2]), "r"(a[3]), "r"(b0), "r"(b1));
}

// ---------------------------------------------------------------------------
// TF32 GEMM core (unchanged from R2): 128x128 tile of A(MxK) * W(NxK)^T
// ---------------------------------------------------------------------------
#define SPITCH 20

__device__ __forceinline__ void tf32_core(const float* __restrict__ A,
                                          const float* __restrict__ W,
                                          int K, float acc[2][8][4])
{
    __shared__ uint32_t As[2][128 * SPITCH];
    __shared__ uint32_t Ws[2][128 * SPITCH];

    const int tid  = threadIdx.x;
    const int lane = tid & 31;
    const int warp = tid >> 5;
    const int wm   = warp & 3;
    const int wn   = warp >> 2;
    const int brow = blockIdx.y * 128;
    const int bcol = blockIdx.x * 128;

    const int lr = tid >> 1;
    const int lk = (tid & 1) * 8;
    const float* Ap = A + (size_t)(brow + lr) * K + lk;
    const float* Wp = W + (size_t)(bcol + lr) * K + lk;

    float4 a0 = *(const float4*)Ap;
    float4 a1 = *(const float4*)(Ap + 4);
    float4 w0 = *(const float4*)Wp;
    float4 w1 = *(const float4*)(Wp + 4);

    auto store_tiles = [&](int buf, float4 va0, float4 va1, float4 vw0, float4 vw1) {
        uint32_t* pa = &As[buf][lr * SPITCH + lk];
        pa[0] = f2tf(va0.x); pa[1] = f2tf(va0.y); pa[2] = f2tf(va0.z); pa[3] = f2tf(va0.w);
        pa[4] = f2tf(va1.x); pa[5] = f2tf(va1.y); pa[6] = f2tf(va1.z); pa[7] = f2tf(va1.w);
        uint32_t* pw = &Ws[buf][lr * SPITCH + lk];
        pw[0] = f2tf(vw0.x); pw[1] = f2tf(vw0.y); pw[2] = f2tf(vw0.z); pw[3] = f2tf(vw0.w);
        pw[4] = f2tf(vw1.x); pw[5] = f2tf(vw1.y); pw[6] = f2tf(vw1.z); pw[7] = f2tf(vw1.w);
    };

    store_tiles(0, a0, a1, w0, w1);
    __syncthreads();

    const int nT = K / 16;
    const int r0 = wm * 32 + (lane >> 2);
    const int cq = lane & 3;

    for (int t = 0; t < nT; ++t) {
        const int cur  = t & 1;
        const int nxt  = cur ^ 1;
        const bool more = (t + 1) < nT;
        if (more) {
            const float* Apn = Ap + (t + 1) * 16;
            const float* Wpn = Wp + (t + 1) * 16;
            a0 = *(const float4*)Apn;
            a1 = *(const float4*)(Apn + 4);
            w0 = *(const float4*)Wpn;
            w1 = *(const float4*)(Wpn + 4);
        }
        #pragma unroll
        for (int kk = 0; kk < 16; kk += 8) {
            const int c0 = kk + cq;
            uint32_t af[2][4];
            #pragma unroll
            for (int mi = 0; mi < 2; ++mi) {
                int rr = r0 + mi * 16;
                af[mi][0] = As[cur][(rr)      * SPITCH + c0];
                af[mi][1] = As[cur][(rr + 8)  * SPITCH + c0];
                af[mi][2] = As[cur][(rr)      * SPITCH + c0 + 4];
                af[mi][3] = As[cur][(rr + 8)  * SPITCH + c0 + 4];
            }
            #pragma unroll
            for (int ni = 0; ni < 8; ++ni) {
                int nb = wn * 64 + ni * 8 + (lane >> 2);
                uint32_t b0 = Ws[cur][nb * SPITCH + c0];
                uint32_t b1 = Ws[cur][nb * SPITCH + c0 + 4];
                mma_tf32(acc[0][ni], af[0], b0, b1);
                mma_tf32(acc[1][ni], af[1], b0, b1);
            }
        }
        if (more) store_tiles(nxt, a0, a1, w0, w1);
        __syncthreads();
    }
}

// ---------------------------------------------------------------------------
// QKV GEMM + scatter epilogue
// ---------------------------------------------------------------------------
__global__ __launch_bounds__(256)
void qkv_kernel(const float* __restrict__ x, const float* __restrict__ qkv_w,
                const float* __restrict__ q_bias, const float* __restrict__ v_bias)
{
    float acc[2][8][4];
    #pragma unroll
    for (int i = 0; i < 2; ++i)
        #pragma unroll
        for (int j = 0; j < 8; ++j)
            #pragma unroll
            for (int k = 0; k < 4; ++k) acc[i][j][k] = 0.f;

    tf32_core(x, qkv_w, C_, acc);

    const int lane = threadIdx.x & 31;
    const int warp = threadIdx.x >> 5;
    const int wm = warp & 3, wn = warp >> 2;
    const int brow = blockIdx.y * 128;
    const int bcol = blockIdx.x * 128;

    const int which = bcol / C_;
    const int ccbase = bcol - which * C_;

    #pragma unroll
    for (int mi = 0; mi < 2; ++mi) {
        #pragma unroll
        for (int rh = 0; rh < 2; ++rh) {
            int row = brow + wm * 32 + mi * 16 + (lane >> 2) + rh * 8;
            int b = row / N_;
            int n = row - b * N_;
            #pragma unroll
            for (int ni = 0; ni < 8; ++ni) {
                #pragma unroll
                for (int cj = 0; cj < 2; ++cj) {
                    int cc = ccbase + wn * 64 + ni * 8 + (lane & 3) * 2 + cj;
                    int h = cc >> 6;
                    int d = cc & 63;
                    size_t dst = (((size_t)(b * H_ + h) * N_) + n) * HD_ + d;
                    float v = acc[mi][ni][rh * 2 + cj];
                    if (which == 0)      g_Q[dst] = (v + q_bias[cc]) * SCALE;
                    else if (which == 1) g_K[dst] = v;
                    else                 g_V[dst] = v + v_bias[cc];
                }
            }
        }
    }
}

// ---------------------------------------------------------------------------
// Proj GEMM + bias epilogue
// ---------------------------------------------------------------------------
__global__ __launch_bounds__(256)
void proj_kernel(const float* __restrict__ proj_w,
                 const float* __restrict__ proj_b, float* __restrict__ out)
{
    float acc[2][8][4];
    #pragma unroll
    for (int i = 0; i < 2; ++i)
        #pragma unroll
        for (int j = 0; j < 8; ++j)
            #pragma unroll
            for (int k = 0; k < 4; ++k) acc[i][j][k] = 0.f;

    tf32_core(g_O, proj_w, C_, acc);

    const int lane = threadIdx.x & 31;
    const int warp = threadIdx.x >> 5;
    const int wm = warp & 3, wn = warp >> 2;
    const int brow = blockIdx.y * 128;
    const int bcol = blockIdx.x * 128;

    #pragma unroll
    for (int mi = 0; mi < 2; ++mi) {
        #pragma unroll
        for (int rh = 0; rh < 2; ++rh) {
            int row = brow + wm * 32 + mi * 16 + (lane >> 2) + rh * 8;
            #pragma unroll
            for (int ni = 0; ni < 8; ++ni) {
                #pragma unroll
                for (int cj = 0; cj < 2; ++cj) {
                    int col = bcol + wn * 64 + ni * 8 + (lane & 3) * 2 + cj;
                    out[(size_t)row * C_ + col] = acc[mi][ni][rh * 2 + cj] + proj_b[col];
                }
            }
        }
    }
}

// ---------------------------------------------------------------------------
// Tensor-core fused attention.
// One CTA per (b,h). K (208x64) and V^T (64x212) smem-resident in tf32.
// 4 q-blocks of 64 rows: QK^T mma -> raw S in smem -> row softmax (+rel bias,
// probs written back as tf32 bits) -> PV mma -> O.
// AP=68 (=4 mod 32), SP=212 (=20 mod 32): conflict-free fragment loads.
// ---------------------------------------------------------------------------
#define AP 68
#define SP 212
#define ATTN_SMEM_WORDS (208 * AP + 64 * SP + 64 * SP + 64 * AP)

__global__ __launch_bounds__(256)
void attn_kernel()
{
    extern __shared__ uint32_t smu[];
    uint32_t* Ks = smu;                      // [208][AP] tf32
    uint32_t* Vt = Ks + 208 * AP;            // [64][SP]  tf32 (V transposed)
    float*    S  = (float*)(Vt + 64 * SP);   // [64][SP]  scores / probs
    uint32_t* Qs = (uint32_t*)S + 64 * SP;   // [64][AP]  tf32

    const int bh = blockIdx.x;
    const int h = bh % H_;
    const int b = bh / H_;
    const int tid = threadIdx.x;
    const int lane = tid & 31;
    const int warp = tid >> 5;
    const int wm = warp & 3;
    const int wn = warp >> 2;

    const float* Kg = g_K + (size_t)bh * N_ * HD_;
    const float* Vg = g_V + (size_t)bh * N_ * HD_;

    for (int i = tid; i < N_ * HD_; i += 256) {
        int m = i >> 6, d = i & 63;
        float kv = Kg[i], vv = Vg[i];
        Ks[m * AP + d] = f2tf(kv);
        Vt[d * SP + m] = f2tf(vv);
    }
    for (int i = tid; i < (208 - N_) * HD_; i += 256) {   // K pad rows
        int m = N_ + (i >> 6), d = i & 63;
        Ks[m * AP + d] = 0;
    }
    for (int i = tid; i < HD_ * (SP - N_); i += 256) {    // Vt pad cols
        int d = i / (SP - N_), m = N_ + i % (SP - N_);
        Vt[d * SP + m] = 0;
    }
    __syncthreads();

    const float* rb = g_RB + (size_t)h * NREL;
    const int r0 = wm * 16 + (lane >> 2);
    const int cq = lane & 3;

    for (int qb = 0; qb < 4; ++qb) {
        // ---- stage Q block ----
        {
            int r = tid >> 2;
            int c0 = (tid & 3) * 16;
            int qg = qb * 64 + r;
            uint32_t* dst = &Qs[r * AP + c0];
            if (qg < N_) {
                const float* qp = g_Q + ((size_t)bh * N_ + qg) * HD_ + c0;
                #pragma unroll
                for (int j = 0; j < 16; j += 4) {
                    float4 v = *(const float4*)(qp + j);
                    dst[j]     = f2tf(v.x);
                    dst[j + 1] = f2tf(v.y);
                    dst[j + 2] = f2tf(v.z);
                    dst[j + 3] = f2tf(v.w);
                }
            } else {
                #pragma unroll
                for (int j = 0; j < 16; ++j) dst[j] = 0;
            }
        }
        __syncthreads();

        // ---- QK^T: 13 n-tiles of 8 per warp ----
        {
            float acc[13][4];
            #pragma unroll
            for (int t = 0; t < 13; ++t)
                #pragma unroll
                for (int k = 0; k < 4; ++k) acc[t][k] = 0.f;

            #pragma unroll
            for (int k = 0; k < 64; k += 8) {
                uint32_t af[4];
                af[0] = Qs[(r0)     * AP + k + cq];
                af[1] = Qs[(r0 + 8) * AP + k + cq];
                af[2] = Qs[(r0)     * AP + k + cq + 4];
                af[3] = Qs[(r0 + 8) * AP + k + cq + 4];
                #pragma unroll
                for (int t = 0; t < 13; ++t) {
                    int nrow = (t * 2 + wn) * 8 + (lane >> 2);
                    uint32_t b0 = Ks[nrow * AP + k + cq];
                    uint32_t b1 = Ks[nrow * AP + k + cq + 4];
                    mma_tf32(acc[t], af, b0, b1);
                }
            }
            #pragma unroll
            for (int t = 0; t < 13; ++t) {
                int n0 = (t * 2 + wn) * 8 + (lane & 3) * 2;
                S[(r0)     * SP + n0]     = acc[t][0];
                S[(r0)     * SP + n0 + 1] = acc[t][1];
                S[(r0 + 8) * SP + n0]     = acc[t][2];
                S[(r0 + 8) * SP + n0 + 1] = acc[t][3];
            }
        }
        __syncthreads();

        // ---- softmax: warp handles rows warp*8 .. warp*8+7 ----
        for (int ri = 0; ri < 8; ++ri) {
            int r = warp * 8 + ri;
            int qg = qb * 64 + r;
            if (lane < SP - N_) S[r * SP + N_ + lane] = 0.0f;  // zero pad cols
            if (qg >= N_) continue;
            const float* rbr = rb + (size_t)qg * N_;
            float s[7];
            float mx = -3.4e38f;
            #pragma unroll
            for (int j = 0; j < 7; ++j) {
                int m = lane + 32 * j;
                s[j] = (m < N_) ? S[r * SP + m] + rbr[m] : -3.4e38f;
                mx = fmaxf(mx, s[j]);
            }
            #pragma unroll
            for (int o = 16; o > 0; o >>= 1)
                mx = fmaxf(mx, __shfl_xor_sync(0xffffffffu, mx, o));
            float sum = 0.f;
            #pragma unroll
            for (int j = 0; j < 7; ++j) {
                s[j] = __expf(s[j] - mx);
                sum += s[j];
            }
            #pragma unroll
            for (int o = 16; o > 0; o >>= 1)
                sum += __shfl_xor_sync(0xffffffffu, sum, o);
            float inv = 1.0f / sum;
            uint32_t* Su = (uint32_t*)S;
            #pragma unroll
            for (int j = 0; j < 7; ++j) {
                int m = lane + 32 * j;
                if (m < N_) Su[r * SP + m] = f2tf(s[j] * inv);
            }
        }
        __syncthreads();

        // ---- PV: 4 d-tiles of 8 per warp ----
        {
            float acc2[4][4];
            #pragma unroll
            for (int t = 0; t < 4; ++t)
                #pragma unroll
                for (int k = 0; k < 4; ++k) acc2[t][k] = 0.f;

            const uint32_t* Su = (const uint32_t*)S;
            #pragma unroll 4
            for (int k = 0; k < 208; k += 8) {
                uint32_t af[4];
                af[0] = Su[(r0)     * SP + k + cq];
                af[1] = Su[(r0 + 8) * SP + k + cq];
                af[2] = Su[(r0)     * SP + k + cq + 4];
                af[3] = Su[(r0 + 8) * SP + k + cq + 4];
                #pragma unroll
                for (int t = 0; t < 4; ++t) {
                    int dn = wn * 32 + t * 8 + (lane >> 2);
                    uint32_t b0 = Vt[dn * SP + k + cq];
                    uint32_t b1 = Vt[dn * SP + k + cq + 4];
                    mma_tf32(acc2[t], af, b0, b1);
                }
            }
            #pragma unroll
            for (int rr = 0; rr < 2; ++rr) {
                int qg = qb * 64 + r0 + rr * 8;
                if (qg < N_) {
                    float* op = g_O + ((size_t)(b * N_ + qg)) * C_ + h * HD_ + wn * 32;
                    #pragma unroll
                    for (int t = 0; t < 4; ++t) {
                        op[t * 8 + (lane & 3) * 2]     = acc2[t][rr * 2];
                        op[t * 8 + (lane & 3) * 2 + 1] = acc2[t][rr * 2 + 1];
                    }
                }
            }
        }
        __syncthreads();
    }
}

// ---------------------------------------------------------------------------
// Launch
// ---------------------------------------------------------------------------
extern "C" void kernel_launch(void* const* d_in, const int* in_sizes, int n_in,
                              void* d_out, int out_size)
{
    (void)in_sizes; (void)n_in; (void)out_size;
    const float* x      = (const float*)d_in[0];
    const float* qkv_w  = (const float*)d_in[1];
    const float* q_bias = (const float*)d_in[2];
    const float* v_bias = (const float*)d_in[3];
    const float* table  = (const float*)d_in[4];
    const float* proj_w = (const float*)d_in[5];
    const float* proj_b = (const float*)d_in[6];
    const int*   ridx   = (const int*)d_in[7];
    float* out = (float*)d_out;

    const int attn_smem = ATTN_SMEM_WORDS * (int)sizeof(uint32_t);
    cudaFuncSetAttribute(attn_kernel,
                         cudaFuncAttributeMaxDynamicSharedMemorySize, attn_smem);

    relbias_kernel<<<(H_ * NREL + 255) / 256, 256>>>(table, ridx);
    qkv_kernel<<<dim3(NC3_ / 128, M_ / 128), 256>>>(x, qkv_w, q_bias, v_bias);
    attn_kernel<<<B_ * H_, 256, attn_smem>>>();
    proj_kernel<<<dim3(C_ / 128, M_ / 128), 256>>>(proj_w, proj_b, out);
}

// round 6
// speedup vs baseline: 2.5165x; 1.3059x over previous
#include <cuda_runtime.h>
#include <cuda_bf16.h>
#include <math.h>
#include <stdint.h>

// Problem constants
#define B_   128
#define N_   197
#define C_   768
#define H_   12
#define HD_  64
#define NC3_ 2304
#define M_   (B_ * N_)     // 25216
#define NREL (38809)
#define SCALE 0.125f

// ---------------------------------------------------------------------------
// Scratch
// ---------------------------------------------------------------------------
__device__ float g_Q[B_ * H_ * N_ * HD_];
__device__ float g_K[B_ * H_ * N_ * HD_];
__device__ float g_V[B_ * H_ * N_ * HD_];
__device__ float g_O[M_ * C_];              // tf32-rounded by attn epilogue
__device__ float g_RB[H_ * NREL];
__device__ float g_xr[M_ * C_];             // tf32-rounded x
__device__ float g_wqkv[NC3_ * C_];         // tf32-rounded qkv_w
__device__ float g_wproj[C_ * C_];          // tf32-rounded proj_w

// ---------------------------------------------------------------------------
// helpers
// ---------------------------------------------------------------------------
__device__ __forceinline__ uint32_t f2tf(float x) {
    uint32_t u;
    asm("cvt.rna.tf32.f32 %0, %1;" : "=r"(u) : "f"(x));
    return u;
}
__device__ __forceinline__ void mma_tf32(float c[4], const uint32_t a[4],
                                         uint32_t b0, uint32_t b1) {
    asm volatile(
        "mma.sync.aligned.m16n8k8.row.col.f32.tf32.tf32.f32 "
        "{%0,%1,%2,%3}, {%4,%5,%6,%7}, {%8,%9}, {%0,%1,%2,%3};"
        : "+f"(c[0]), "+f"(c[1]), "+f"(c[2]), "+f"(c[3])
        : "r"(a[0]), "r"(a[1]), "r"(a[2]), "r"(a[3]), "r"(b0), "r"(b1));
}
__device__ __forceinline__ uint32_t smem_u32(const void* p) {
    return (uint32_t)__cvta_generic_to_shared(p);
}
__device__ __forceinline__ void cpasync16(uint32_t dst, const void* src) {
    asm volatile("cp.async.cg.shared.global [%0], [%1], 16;" :: "r"(dst), "l"(src));
}
__device__ __forceinline__ void cp_commit() {
    asm volatile("cp.async.commit_group;");
}
template <int Nn> __device__ __forceinline__ void cp_wait() {
    asm volatile("cp.async.wait_group %0;" :: "n"(Nn));
}
__device__ __forceinline__ void ldsm4(uint32_t& r0, uint32_t& r1,
                                      uint32_t& r2, uint32_t& r3, uint32_t a) {
    asm volatile("ldmatrix.sync.aligned.m8n8.x4.shared.b16 {%0,%1,%2,%3}, [%4];"
                 : "=r"(r0), "=r"(r1), "=r"(r2), "=r"(r3) : "r"(a));
}
__device__ __forceinline__ void ldsm2(uint32_t& r0, uint32_t& r1, uint32_t a) {
    asm volatile("ldmatrix.sync.aligned.m8n8.x2.shared.b16 {%0,%1}, [%2];"
                 : "=r"(r0), "=r"(r1) : "r"(a));
}

// ---------------------------------------------------------------------------
// tf32 pre-round (RNA) kernel: dst = round_tf32(src), vectorized
// ---------------------------------------------------------------------------
__global__ void round_kernel(const float* __restrict__ s, float* __restrict__ d, int n4) {
    int i = blockIdx.x * 256 + threadIdx.x;
    if (i < n4) {
        float4 v = ((const float4*)s)[i];
        v.x = __uint_as_float(f2tf(v.x));
        v.y = __uint_as_float(f2tf(v.y));
        v.z = __uint_as_float(f2tf(v.z));
        v.w = __uint_as_float(f2tf(v.w));
        ((float4*)d)[i] = v;
    }
}

// ---------------------------------------------------------------------------
// relbias gather
// ---------------------------------------------------------------------------
__global__ void relbias_kernel(const float* __restrict__ table,
                               const int* __restrict__ idx) {
    int i = blockIdx.x * 256 + threadIdx.x;
    if (i < H_ * NREL) {
        int h = i / NREL;
        int r = i - h * NREL;
        g_RB[i] = table[idx[r] * H_ + h];
    }
}

// ---------------------------------------------------------------------------
// Pipelined TF32 GEMM core: 128x128 tile of A(MxK) * W(NxK)^T.
// BK=32, 3-stage cp.async, SW128 xor swizzle, ldmatrix fragment loads.
// 8 warps (4M x 2N), warp tile 32x64. Inputs must be pre-rounded to tf32.
// ---------------------------------------------------------------------------
#define NSTG 3
#define OPW_BYTES 16384            // one operand block: 128 rows * 128 B
#define STG_BYTES 32768            // two operand blocks
#define GEMM_SMEM (NSTG * STG_BYTES)

__device__ __forceinline__ void tf32_core_pipe(
    const float* __restrict__ A, const float* __restrict__ W,
    int K, float acc[2][8][4])
{
    extern __shared__ uint32_t smp[];
    const uint32_t base = smem_u32(smp);

    const int tid = threadIdx.x;
    const int lane = tid & 31;
    const int warp = tid >> 5;
    const int wm = warp & 3, wn = warp >> 2;
    const int brow = blockIdx.y * 128;
    const int bcol = blockIdx.x * 128;

    // cp.async mapping: thread -> (row = tid/2, 4 x 16B segs)
    const int r = tid >> 1;
    const int sh = (tid & 1) * 4;
    const float* Ag = A + (size_t)(brow + r) * K + sh * 4;
    const float* Wg = W + (size_t)(bcol + r) * K + sh * 4;
    uint32_t dA[4], dW[4];
    #pragma unroll
    for (int j = 0; j < 4; ++j) {
        int col = (sh + j) ^ (r & 7);
        dA[j] = base + r * 128 + col * 16;
        dW[j] = base + OPW_BYTES + r * 128 + col * 16;
    }

    const int nT = K / 32;

    auto issue = [&](int t) {
        uint32_t so = (uint32_t)(t % NSTG) * STG_BYTES;
        const float* ga = Ag + t * 32;
        const float* gw = Wg + t * 32;
        #pragma unroll
        for (int j = 0; j < 4; ++j) cpasync16(dA[j] + so, ga + j * 4);
        #pragma unroll
        for (int j = 0; j < 4; ++j) cpasync16(dW[j] + so, gw + j * 4);
        cp_commit();
    };

    issue(0);
    issue(1);

    // ldmatrix per-thread bases
    const int ti = lane >> 3, rsub = lane & 7;
    uint32_t aB[2]; int rwA[2];
    #pragma unroll
    for (int mi = 0; mi < 2; ++mi) {
        int rr = wm * 32 + mi * 16 + ((ti & 1) << 3) + rsub;
        rwA[mi] = rr & 7;
        aB[mi] = base + rr * 128;
    }
    const int kgbA = ti >> 1;
    uint32_t bB[4]; int rwB[4];
    #pragma unroll
    for (int p = 0; p < 4; ++p) {
        int rr = wn * 64 + p * 16 + ((ti >> 1) << 3) + rsub;
        rwB[p] = rr & 7;
        bB[p] = base + OPW_BYTES + rr * 128;
    }
    const int kgbB = ti & 1;

    for (int t = 0; t < nT; ++t) {
        if (t + 1 < nT) cp_wait<1>(); else cp_wait<0>();
        __syncthreads();
        if (t + 2 < nT) issue(t + 2);
        const uint32_t so = (uint32_t)(t % NSTG) * STG_BYTES;
        #pragma unroll
        for (int kk = 0; kk < 4; ++kk) {
            uint32_t af[2][4];
            #pragma unroll
            for (int mi = 0; mi < 2; ++mi) {
                uint32_t addr = aB[mi] + so +
                    (uint32_t)((((2 * kk + kgbA) ^ rwA[mi]) & 7) << 4);
                ldsm4(af[mi][0], af[mi][1], af[mi][2], af[mi][3], addr);
            }
            #pragma unroll
            for (int p = 0; p < 4; ++p) {
                uint32_t b0a, b1a, b0b, b1b;
                uint32_t addr = bB[p] + so +
                    (uint32_t)((((2 * kk + kgbB) ^ rwB[p]) & 7) << 4);
                ldsm4(b0a, b1a, b0b, b1b, addr);
                mma_tf32(acc[0][2 * p],     af[0], b0a, b1a);
                mma_tf32(acc[1][2 * p],     af[1], b0a, b1a);
                mma_tf32(acc[0][2 * p + 1], af[0], b0b, b1b);
                mma_tf32(acc[1][2 * p + 1], af[1], b0b, b1b);
            }
        }
    }
}

// ---------------------------------------------------------------------------
// QKV GEMM + scatter epilogue
// ---------------------------------------------------------------------------
__global__ __launch_bounds__(256, 2)
void qkv_kernel(const float* __restrict__ q_bias, const float* __restrict__ v_bias)
{
    float acc[2][8][4];
    #pragma unroll
    for (int i = 0; i < 2; ++i)
        #pragma unroll
        for (int j = 0; j < 8; ++j)
            #pragma unroll
            for (int k = 0; k < 4; ++k) acc[i][j][k] = 0.f;

    tf32_core_pipe(g_xr, g_wqkv, C_, acc);

    const int lane = threadIdx.x & 31;
    const int warp = threadIdx.x >> 5;
    const int wm = warp & 3, wn = warp >> 2;
    const int brow = blockIdx.y * 128;
    const int bcol = blockIdx.x * 128;

    const int which = bcol / C_;
    const int ccbase = bcol - which * C_;

    #pragma unroll
    for (int mi = 0; mi < 2; ++mi) {
        #pragma unroll
        for (int rh = 0; rh < 2; ++rh) {
            int row = brow + wm * 32 + mi * 16 + (lane >> 2) + rh * 8;
            int b = row / N_;
            int n = row - b * N_;
            #pragma unroll
            for (int ni = 0; ni < 8; ++ni) {
                #pragma unroll
                for (int cj = 0; cj < 2; ++cj) {
                    int cc = ccbase + wn * 64 + ni * 8 + (lane & 3) * 2 + cj;
                    int h = cc >> 6;
                    int d = cc & 63;
                    size_t dst = (((size_t)(b * H_ + h) * N_) + n) * HD_ + d;
                    float v = acc[mi][ni][rh * 2 + cj];
                    if (which == 0)      g_Q[dst] = (v + q_bias[cc]) * SCALE;
                    else if (which == 1) g_K[dst] = v;
                    else                 g_V[dst] = v + v_bias[cc];
                }
            }
        }
    }
}

// ---------------------------------------------------------------------------
// Proj GEMM + bias epilogue
// ---------------------------------------------------------------------------
__global__ __launch_bounds__(256, 2)
void proj_kernel(const float* __restrict__ proj_b, float* __restrict__ out)
{
    float acc[2][8][4];
    #pragma unroll
    for (int i = 0; i < 2; ++i)
        #pragma unroll
        for (int j = 0; j < 8; ++j)
            #pragma unroll
            for (int k = 0; k < 4; ++k) acc[i][j][k] = 0.f;

    tf32_core_pipe(g_O, g_wproj, C_, acc);

    const int lane = threadIdx.x & 31;
    const int warp = threadIdx.x >> 5;
    const int wm = warp & 3, wn = warp >> 2;
    const int brow = blockIdx.y * 128;
    const int bcol = blockIdx.x * 128;

    #pragma unroll
    for (int mi = 0; mi < 2; ++mi) {
        #pragma unroll
        for (int rh = 0; rh < 2; ++rh) {
            int row = brow + wm * 32 + mi * 16 + (lane >> 2) + rh * 8;
            #pragma unroll
            for (int ni = 0; ni < 8; ++ni) {
                #pragma unroll
                for (int cj = 0; cj < 2; ++cj) {
                    int col = bcol + wn * 64 + ni * 8 + (lane & 3) * 2 + cj;
                    out[(size_t)row * C_ + col] = acc[mi][ni][rh * 2 + cj] + proj_b[col];
                }
            }
        }
    }
}

// ---------------------------------------------------------------------------
// Tensor-core fused attention (ldmatrix fragment loads).
// One CTA per (b,h). Pitches: AP=68, SP=212 (LDSM conflict-free).
// ---------------------------------------------------------------------------
#define AP 68
#define SP 212
#define ATTN_SMEM_WORDS (208 * AP + 64 * SP + 64 * SP + 64 * AP)

__global__ __launch_bounds__(256)
void attn_kernel()
{
    extern __shared__ uint32_t smu[];
    uint32_t* Ks = smu;                      // [208][AP] tf32
    uint32_t* Vt = Ks + 208 * AP;            // [64][SP]  tf32 (V transposed)
    float*    S  = (float*)(Vt + 64 * SP);   // [64][SP]  scores / probs
    uint32_t* Qs = (uint32_t*)S + 64 * SP;   // [64][AP]  tf32

    const uint32_t KsB = smem_u32(Ks);
    const uint32_t VtB = smem_u32(Vt);
    const uint32_t SB  = smem_u32(S);
    const uint32_t QsB = smem_u32(Qs);

    const int bh = blockIdx.x;
    const int h = bh % H_;
    const int b = bh / H_;
    const int tid = threadIdx.x;
    const int lane = tid & 31;
    const int warp = tid >> 5;
    const int wm = warp & 3;
    const int wn = warp >> 2;

    const float* Kg = g_K + (size_t)bh * N_ * HD_;
    const float* Vg = g_V + (size_t)bh * N_ * HD_;

    for (int i = tid; i < N_ * HD_; i += 256) {
        int m = i >> 6, d = i & 63;
        Ks[m * AP + d] = f2tf(Kg[i]);
        Vt[d * SP + m] = f2tf(Vg[i]);
    }
    for (int i = tid; i < (208 - N_) * HD_; i += 256) {
        int m = N_ + (i >> 6), d = i & 63;
        Ks[m * AP + d] = 0;
    }
    for (int i = tid; i < HD_ * (SP - N_); i += 256) {
        int d = i / (SP - N_), m = N_ + i % (SP - N_);
        Vt[d * SP + m] = 0;
    }
    __syncthreads();

    const float* rb = g_RB + (size_t)h * NREL;
    const int r0 = wm * 16 + (lane >> 2);
    const int ti = lane >> 3, rsub = lane & 7;

    // ldmatrix bases (kk-invariant parts)
    const uint32_t qA = QsB + (uint32_t)((wm * 16 + ((ti & 1) << 3) + rsub) * AP) * 4
                            + (uint32_t)(ti >> 1) * 16;
    uint32_t kB[6];
    #pragma unroll
    for (int q = 0; q < 6; ++q)
        kB[q] = KsB + (uint32_t)(((4 * q + 2 * (ti >> 1) + wn) * 8 + rsub) * AP) * 4
                    + (uint32_t)(ti & 1) * 16;
    const uint32_t kB12 = KsB + (uint32_t)(((24 + wn) * 8 + (lane & 7)) * AP) * 4
                              + (uint32_t)((lane >> 3) & 1) * 16;
    const uint32_t sA = SB + (uint32_t)((wm * 16 + ((ti & 1) << 3) + rsub) * SP) * 4
                           + (uint32_t)(ti >> 1) * 16;
    uint32_t vB[2];
    #pragma unroll
    for (int q = 0; q < 2; ++q)
        vB[q] = VtB + (uint32_t)((wn * 32 + q * 16 + ((ti >> 1) << 3) + rsub) * SP) * 4
                    + (uint32_t)(ti & 1) * 16;

    for (int qb = 0; qb < 4; ++qb) {
        // ---- stage Q block ----
        {
            int r = tid >> 2;
            int c0 = (tid & 3) * 16;
            int qg = qb * 64 + r;
            uint32_t* dst = &Qs[r * AP + c0];
            if (qg < N_) {
                const float* qp = g_Q + ((size_t)bh * N_ + qg) * HD_ + c0;
                #pragma unroll
                for (int j = 0; j < 16; j += 4) {
                    float4 v = *(const float4*)(qp + j);
                    dst[j]     = f2tf(v.x);
                    dst[j + 1] = f2tf(v.y);
                    dst[j + 2] = f2tf(v.z);
                    dst[j + 3] = f2tf(v.w);
                }
            } else {
                #pragma unroll
                for (int j = 0; j < 16; ++j) dst[j] = 0;
            }
        }
        __syncthreads();

        // ---- QK^T ----
        {
            float acc[13][4];
            #pragma unroll
            for (int t = 0; t < 13; ++t)
                #pragma unroll
                for (int k = 0; k < 4; ++k) acc[t][k] = 0.f;

            #pragma unroll
            for (int kk = 0; kk < 8; ++kk) {
                uint32_t af[4];
                ldsm4(af[0], af[1], af[2], af[3], qA + kk * 32);
                #pragma unroll
                for (int q = 0; q < 6; ++q) {
                    uint32_t b0a, b1a, b0b, b1b;
                    ldsm4(b0a, b1a, b0b, b1b, kB[q] + kk * 32);
                    mma_tf32(acc[2 * q],     af, b0a, b1a);
                    mma_tf32(acc[2 * q + 1], af, b0b, b1b);
                }
                uint32_t c0, c1;
                ldsm2(c0, c1, kB12 + kk * 32);
                mma_tf32(acc[12], af, c0, c1);
            }
            #pragma unroll
            for (int t = 0; t < 13; ++t) {
                int n0 = (t * 2 + wn) * 8 + (lane & 3) * 2;
                S[(r0)     * SP + n0]     = acc[t][0];
                S[(r0)     * SP + n0 + 1] = acc[t][1];
                S[(r0 + 8) * SP + n0]     = acc[t][2];
                S[(r0 + 8) * SP + n0 + 1] = acc[t][3];
            }
        }
        __syncthreads();

        // ---- softmax ----
        for (int ri = 0; ri < 8; ++ri) {
            int r = warp * 8 + ri;
            int qg = qb * 64 + r;
            if (lane < SP - N_) S[r * SP + N_ + lane] = 0.0f;
            if (qg >= N_) continue;
            const float* rbr = rb + (size_t)qg * N_;
            float s[7];
            float mx = -3.4e38f;
            #pragma unroll
            for (int j = 0; j < 7; ++j) {
                int m = lane + 32 * j;
                s[j] = (m < N_) ? S[r * SP + m] + rbr[m] : -3.4e38f;
                mx = fmaxf(mx, s[j]);
            }
            #pragma unroll
            for (int o = 16; o > 0; o >>= 1)
                mx = fmaxf(mx, __shfl_xor_sync(0xffffffffu, mx, o));
            float sum = 0.f;
            #pragma unroll
            for (int j = 0; j < 7; ++j) {
                s[j] = __expf(s[j] - mx);
                sum += s[j];
            }
            #pragma unroll
            for (int o = 16; o > 0; o >>= 1)
                sum += __shfl_xor_sync(0xffffffffu, sum, o);
            float inv = 1.0f / sum;
            uint32_t* Su = (uint32_t*)S;
            #pragma unroll
            for (int j = 0; j < 7; ++j) {
                int m = lane + 32 * j;
                if (m < N_) Su[r * SP + m] = f2tf(s[j] * inv);
            }
        }
        __syncthreads();

        // ---- PV ----
        {
            float acc2[4][4];
            #pragma unroll
            for (int t = 0; t < 4; ++t)
                #pragma unroll
                for (int k = 0; k < 4; ++k) acc2[t][k] = 0.f;

            #pragma unroll 2
            for (int kk = 0; kk < 26; ++kk) {
                uint32_t af[4];
                ldsm4(af[0], af[1], af[2], af[3], sA + kk * 32);
                #pragma unroll
                for (int q = 0; q < 2; ++q) {
                    uint32_t b0a, b1a, b0b, b1b;
                    ldsm4(b0a, b1a, b0b, b1b, vB[q] + kk * 32);
                    mma_tf32(acc2[2 * q],     af, b0a, b1a);
                    mma_tf32(acc2[2 * q + 1], af, b0b, b1b);
                }
            }
            #pragma unroll
            for (int rr = 0; rr < 2; ++rr) {
                int qg = qb * 64 + r0 + rr * 8;
                if (qg < N_) {
                    float* op = g_O + ((size_t)(b * N_ + qg)) * C_ + h * HD_ + wn * 32;
                    #pragma unroll
                    for (int t = 0; t < 4; ++t) {
                        op[t * 8 + (lane & 3) * 2] =
                            __uint_as_float(f2tf(acc2[t][rr * 2]));
                        op[t * 8 + (lane & 3) * 2 + 1] =
                            __uint_as_float(f2tf(acc2[t][rr * 2 + 1]));
                    }
                }
            }
        }
        __syncthreads();
    }
}

// ---------------------------------------------------------------------------
// Launch
// ---------------------------------------------------------------------------
extern "C" void kernel_launch(void* const* d_in, const int* in_sizes, int n_in,
                              void* d_out, int out_size)
{
    (void)in_sizes; (void)n_in; (void)out_size;
    const float* x      = (const float*)d_in[0];
    const float* qkv_w  = (const float*)d_in[1];
    const float* q_bias = (const float*)d_in[2];
    const float* v_bias = (const float*)d_in[3];
    const float* table  = (const float*)d_in[4];
    const float* proj_w = (const float*)d_in[5];
    const float* proj_b = (const float*)d_in[6];
    const int*   ridx   = (const int*)d_in[7];
    float* out = (float*)d_out;

    const int attn_smem = ATTN_SMEM_WORDS * (int)sizeof(uint32_t);
    cudaFuncSetAttribute(attn_kernel,
                         cudaFuncAttributeMaxDynamicSharedMemorySize, attn_smem);
    cudaFuncSetAttribute(qkv_kernel,
                         cudaFuncAttributeMaxDynamicSharedMemorySize, GEMM_SMEM);
    cudaFuncSetAttribute(proj_kernel,
                         cudaFuncAttributeMaxDynamicSharedMemorySize, GEMM_SMEM);

    // pre-round inputs to tf32 (RNA) so cp.async path keeps exact numerics
    {
        float* xr = nullptr; cudaGetSymbolAddress((void**)&xr, g_xr);
        float* wq = nullptr; cudaGetSymbolAddress((void**)&wq, g_wqkv);
        float* wp = nullptr; cudaGetSymbolAddress((void**)&wp, g_wproj);
        int n4x = M_ * C_ / 4, n4q = NC3_ * C_ / 4, n4p = C_ * C_ / 4;
        round_kernel<<<(n4x + 255) / 256, 256>>>(x, xr, n4x);
        round_kernel<<<(n4q + 255) / 256, 256>>>(qkv_w, wq, n4q);
        round_kernel<<<(n4p + 255) / 256, 256>>>(proj_w, wp, n4p);
    }

    relbias_kernel<<<(H_ * NREL + 255) / 256, 256>>>(table, ridx);
    qkv_kernel<<<dim3(NC3_ / 128, M_ / 128), 256, GEMM_SMEM>>>(q_bias, v_bias);
    attn_kernel<<<B_ * H_, 256, attn_smem>>>();
    proj_kernel<<<dim3(C_ / 128, M_ / 128), 256, GEMM_SMEM>>>(proj_b, out);
}